// round 2
// baseline (speedup 1.0000x reference)
#include <cuda_runtime.h>

#define NN 4096
#define DD 1024
#define TS 64
#define TK 16
#define SST 68  // padded smem row stride (floats); 68*4B is 16B-aligned

// Scratch (allocation-free: __device__ globals)
__device__ float g_xm[NN * DD];   // x_l @ M   (16 MB)
__device__ float g_linl[NN];
__device__ float g_linr[NN];

// ---------------------------------------------------------------------------
// lin_l[row] = dot(x_l[row], wl) + bl ; lin_r analogous. One block per row.
// Grid: 2*NN blocks of 256 threads (first NN = left, second NN = right).
// ---------------------------------------------------------------------------
__global__ __launch_bounds__(256) void lin_kernel(
    const float* __restrict__ xl, const float* __restrict__ xr,
    const float* __restrict__ wl, const float* __restrict__ bl,
    const float* __restrict__ wr, const float* __restrict__ br)
{
    __shared__ float red[256];
    int row = blockIdx.x;
    int right = (row >= NN);
    if (right) row -= NN;
    const float* x = right ? xr : xl;
    const float* w = right ? wr : wl;

    float s = 0.f;
    for (int k = threadIdx.x; k < DD; k += 256)
        s += x[row * DD + k] * w[k];
    red[threadIdx.x] = s;
    __syncthreads();
    for (int off = 128; off > 0; off >>= 1) {
        if (threadIdx.x < off) red[threadIdx.x] += red[threadIdx.x + off];
        __syncthreads();
    }
    if (threadIdx.x == 0) {
        float v = red[0] + (right ? br[0] : bl[0]);
        if (right) g_linr[row] = v;
        else       g_linl[row] = v;
    }
}

// ---------------------------------------------------------------------------
// GEMM NN: g_xm[n,d] = sum_k x_l[n,k] * M[k,d]
// A row-major [NN,DD], B row-major [DD,DD]. 64x64 tile, TK=16, 256 threads,
// 4x4 micro-tile per thread. A staged transposed in smem, B staged direct.
// Grid: (DD/64, NN/64)
// ---------------------------------------------------------------------------
__global__ __launch_bounds__(256) void gemm_nn(
    const float* __restrict__ A, const float* __restrict__ B)
{
    __shared__ float As[TK][SST];
    __shared__ float Bs[TK][SST];

    const int t  = threadIdx.x;
    const int tx = t & 15, ty = t >> 4;
    const int rowBase = blockIdx.y * TS;
    const int colBase = blockIdx.x * TS;

    // A load mapping: 256 threads -> 64 rows x (16k as 4 float4)
    const int aRow = t >> 2;
    const int aK4  = (t & 3) * 4;
    // B load mapping: 16 k-rows x 16 float4 columns
    const int bK  = t >> 4;
    const int bC4 = (t & 15) * 4;

    float acc[4][4] = {};

    for (int k0 = 0; k0 < DD; k0 += TK) {
        float4 av = *(const float4*)&A[(size_t)(rowBase + aRow) * DD + k0 + aK4];
        As[aK4 + 0][aRow] = av.x;
        As[aK4 + 1][aRow] = av.y;
        As[aK4 + 2][aRow] = av.z;
        As[aK4 + 3][aRow] = av.w;
        float4 bv = *(const float4*)&B[(size_t)(k0 + bK) * DD + colBase + bC4];
        *(float4*)&Bs[bK][bC4] = bv;
        __syncthreads();

        #pragma unroll
        for (int k = 0; k < TK; k++) {
            float4 a = *(const float4*)&As[k][ty * 4];
            float4 b = *(const float4*)&Bs[k][tx * 4];
            float ar[4] = {a.x, a.y, a.z, a.w};
            float bb[4] = {b.x, b.y, b.z, b.w};
            #pragma unroll
            for (int i = 0; i < 4; i++)
                #pragma unroll
                for (int j = 0; j < 4; j++)
                    acc[i][j] += ar[i] * bb[j];
        }
        __syncthreads();
    }

    #pragma unroll
    for (int i = 0; i < 4; i++) {
        float4 v = make_float4(acc[i][0], acc[i][1], acc[i][2], acc[i][3]);
        *(float4*)&g_xm[(size_t)(rowBase + ty * 4 + i) * DD + colBase + tx * 4] = v;
    }
}

// ---------------------------------------------------------------------------
// GEMM NT + epilogue:
//   S[n,m] = sum_k g_xm[n,k] * x_r[m,k] + bias + linl[n] + linr[m]
//   S = relu(S); out[0..N*N) = mask ? S : 0 ; out[N*N..2N*N) = S (if present)
// mask is int32 (bool upcast by harness).
// Grid: (NN/64, NN/64)
// ---------------------------------------------------------------------------
__global__ __launch_bounds__(256) void gemm_nt_epi(
    const float* __restrict__ Bm /* x_r */,
    const int* __restrict__ mask,
    const float* __restrict__ bias,
    float* __restrict__ out,
    int write_x_half)
{
    __shared__ float As[TK][SST];
    __shared__ float Bs[TK][SST];

    const int t  = threadIdx.x;
    const int tx = t & 15, ty = t >> 4;
    const int rowBase = blockIdx.y * TS;
    const int colBase = blockIdx.x * TS;

    const int lRow = t >> 2;
    const int lK4  = (t & 3) * 4;

    float acc[4][4] = {};

    for (int k0 = 0; k0 < DD; k0 += TK) {
        float4 av = *(const float4*)&g_xm[(size_t)(rowBase + lRow) * DD + k0 + lK4];
        As[lK4 + 0][lRow] = av.x;
        As[lK4 + 1][lRow] = av.y;
        As[lK4 + 2][lRow] = av.z;
        As[lK4 + 3][lRow] = av.w;
        float4 bv = *(const float4*)&Bm[(size_t)(colBase + lRow) * DD + k0 + lK4];
        Bs[lK4 + 0][lRow] = bv.x;
        Bs[lK4 + 1][lRow] = bv.y;
        Bs[lK4 + 2][lRow] = bv.z;
        Bs[lK4 + 3][lRow] = bv.w;
        __syncthreads();

        #pragma unroll
        for (int k = 0; k < TK; k++) {
            float4 a = *(const float4*)&As[k][ty * 4];
            float4 b = *(const float4*)&Bs[k][tx * 4];
            float ar[4] = {a.x, a.y, a.z, a.w};
            float bb[4] = {b.x, b.y, b.z, b.w};
            #pragma unroll
            for (int i = 0; i < 4; i++)
                #pragma unroll
                for (int j = 0; j < 4; j++)
                    acc[i][j] += ar[i] * bb[j];
        }
        __syncthreads();
    }

    const float b0 = bias[0];
    const int colG = colBase + tx * 4;
    float lr[4];
    #pragma unroll
    for (int j = 0; j < 4; j++) lr[j] = g_linr[colG + j];

    const size_t xoff = (size_t)NN * NN;
    #pragma unroll
    for (int i = 0; i < 4; i++) {
        int rowG = rowBase + ty * 4 + i;
        float ll = g_linl[rowG];
        float v[4];
        #pragma unroll
        for (int j = 0; j < 4; j++) {
            float s = acc[i][j] + b0 + ll + lr[j];
            v[j] = s > 0.f ? s : 0.f;
        }
        size_t base = (size_t)rowG * NN + colG;
        if (write_x_half) {
            float4 xv = make_float4(v[0], v[1], v[2], v[3]);
            *(float4*)&out[xoff + base] = xv;
        }
        // masked scores: mask is int32 {0,1}
        int4 mv = *(const int4*)&mask[base];
        float4 sv = make_float4(mv.x ? v[0] : 0.f,
                                mv.y ? v[1] : 0.f,
                                mv.z ? v[2] : 0.f,
                                mv.w ? v[3] : 0.f);
        *(float4*)&out[base] = sv;
    }
}

// ---------------------------------------------------------------------------
extern "C" void kernel_launch(void* const* d_in, const int* in_sizes, int n_in,
                              void* d_out, int out_size)
{
    const float* xl     = (const float*)d_in[0];
    const float* xr     = (const float*)d_in[1];
    const int*   mask   = (const int*)d_in[2];
    const float* matrix = (const float*)d_in[3];
    const float* bias   = (const float*)d_in[4];
    const float* wl     = (const float*)d_in[5];
    const float* bl     = (const float*)d_in[6];
    const float* wr     = (const float*)d_in[7];
    const float* br     = (const float*)d_in[8];
    float* out = (float*)d_out;

    int write_x_half = (out_size >= 2 * NN * NN) ? 1 : 0;

    // 1) linear terms
    lin_kernel<<<2 * NN, 256>>>(xl, xr, wl, bl, wr, br);

    // 2) XM = x_l @ M
    {
        dim3 grid(DD / TS, NN / TS);
        gemm_nn<<<grid, 256>>>(xl, matrix);
    }

    // 3) S = XM @ x_r^T + epilogue
    {
        dim3 grid(NN / TS, NN / TS);
        gemm_nt_epi<<<grid, 256>>>(xr, mask, bias, out, write_x_half);
    }
}

// round 4
// speedup vs baseline: 2.0945x; 2.0945x over previous
#include <cuda_runtime.h>
#include <cstdint>

#define NN 4096
#define DD 1024
#define BM 128
#define BN 128
#define BK 32
#define PAD 36   // smem row stride (floats): bank = 4*r + c -> conflict-free frags

// Scratch (allocation-free: __device__ globals)
__device__ float g_xm[NN * DD];   // x_l @ M  (16 MB)
__device__ float g_mt[DD * DD];   // M^T      (4 MB)
__device__ float g_linl[NN];
__device__ float g_linr[NN];

__device__ __forceinline__ float tf32r(float x) {
    uint32_t y;
    asm("cvt.rna.tf32.f32 %0, %1;" : "=r"(y) : "f"(x));
    return __uint_as_float(y);
}

// ---------------------------------------------------------------------------
// lin terms: warp per row, float4 + shfl. Grid: 1024 blocks x 256.
// ---------------------------------------------------------------------------
__global__ __launch_bounds__(256) void lin_kernel(
    const float* __restrict__ xl, const float* __restrict__ xr,
    const float* __restrict__ wl, const float* __restrict__ bl,
    const float* __restrict__ wr, const float* __restrict__ br)
{
    int gw   = (blockIdx.x * 256 + threadIdx.x) >> 5;
    int lane = threadIdx.x & 31;
    int right = gw >= NN;
    int row = right ? gw - NN : gw;
    const float* x = right ? xr : xl;
    const float* w = right ? wr : wl;
    const float4* xv = (const float4*)(x + (size_t)row * DD);
    const float4* wv = (const float4*)w;
    float s = 0.f;
    #pragma unroll
    for (int i = 0; i < 8; i++) {
        float4 a = xv[lane + i * 32];
        float4 b = wv[lane + i * 32];
        s += a.x * b.x + a.y * b.y + a.z * b.z + a.w * b.w;
    }
    #pragma unroll
    for (int o = 16; o; o >>= 1) s += __shfl_xor_sync(0xffffffffu, s, o);
    if (lane == 0) {
        if (right) g_linr[row] = s + br[0];
        else       g_linl[row] = s + bl[0];
    }
}

// ---------------------------------------------------------------------------
// M[k][n] -> g_mt[n][k]. Grid (32,32), block (32,8).
// ---------------------------------------------------------------------------
__global__ void transpose_kernel(const float* __restrict__ in)
{
    __shared__ float tile[32][33];
    int x = blockIdx.x * 32 + threadIdx.x;
    int y = blockIdx.y * 32 + threadIdx.y;
    #pragma unroll
    for (int i = 0; i < 32; i += 8)
        tile[threadIdx.y + i][threadIdx.x] = in[(size_t)(y + i) * DD + x];
    __syncthreads();
    x = blockIdx.y * 32 + threadIdx.x;
    y = blockIdx.x * 32 + threadIdx.y;
    #pragma unroll
    for (int i = 0; i < 32; i += 8)
        g_mt[(size_t)(y + i) * DD + x] = tile[threadIdx.x][threadIdx.y + i];
}

// ---------------------------------------------------------------------------
// tf32 NT GEMM: C[m,n] = sum_k A[m,k] * B[n,k], K = 1024.
// A row-major lda=1024, B row-major ldb=1024 (K contiguous in both).
// Block 128x128x32, 8 warps (4 M x 2 N), warp tile 32x64, mma m16n8k8.
// do_epi=0: raw store to Cout (ld = Ncols).
// do_epi=1: v=relu(c+bias+linl[m]+linr[n]); out[m,n]=mask?v:0; out2[m,n]=v.
// ---------------------------------------------------------------------------
__global__ __launch_bounds__(256) void gemm_tf32(
    const float* __restrict__ A, const float* __restrict__ B,
    int Ncols, float* __restrict__ Cout,
    const int* __restrict__ mask, const float* __restrict__ bias,
    int do_epi, int write_x_half)
{
    __shared__ float As[BM][PAD];
    __shared__ float Bs[BN][PAD];

    const int t    = threadIdx.x;
    const int lane = t & 31;
    const int wid  = t >> 5;
    const int wm   = wid >> 1;      // 0..3
    const int wn   = wid & 1;       // 0..1
    const int g    = lane >> 2;     // 0..7
    const int q    = lane & 3;      // 0..3

    const int rowBase = blockIdx.y * BM;
    const int colBase = blockIdx.x * BN;

    float c[2][8][4];
    #pragma unroll
    for (int mm = 0; mm < 2; mm++)
        #pragma unroll
        for (int nn = 0; nn < 8; nn++)
            #pragma unroll
            for (int r = 0; r < 4; r++) c[mm][nn][r] = 0.f;

    for (int k0 = 0; k0 < DD; k0 += BK) {
        // stage tiles (tf32-rounded): 1024 float4 each, 4 per thread
        #pragma unroll
        for (int i = 0; i < 4; i++) {
            int idx = i * 256 + t;
            int r   = idx >> 3;
            int k4  = (idx & 7) * 4;
            float4 av = *(const float4*)&A[(size_t)(rowBase + r) * DD + k0 + k4];
            As[r][k4 + 0] = tf32r(av.x);
            As[r][k4 + 1] = tf32r(av.y);
            As[r][k4 + 2] = tf32r(av.z);
            As[r][k4 + 3] = tf32r(av.w);
            float4 bv = *(const float4*)&B[(size_t)(colBase + r) * DD + k0 + k4];
            Bs[r][k4 + 0] = tf32r(bv.x);
            Bs[r][k4 + 1] = tf32r(bv.y);
            Bs[r][k4 + 2] = tf32r(bv.z);
            Bs[r][k4 + 3] = tf32r(bv.w);
        }
        __syncthreads();

        #pragma unroll
        for (int ks = 0; ks < 4; ks++) {
            int kb = ks * 8;
            float a[2][4];
            #pragma unroll
            for (int mm = 0; mm < 2; mm++) {
                int r = wm * 32 + mm * 16 + g;
                a[mm][0] = As[r][kb + q];
                a[mm][1] = As[r + 8][kb + q];
                a[mm][2] = As[r][kb + q + 4];
                a[mm][3] = As[r + 8][kb + q + 4];
            }
            #pragma unroll
            for (int nn = 0; nn < 8; nn++) {
                int n = wn * 64 + nn * 8 + g;
                float b0 = Bs[n][kb + q];
                float b1 = Bs[n][kb + q + 4];
                #pragma unroll
                for (int mm = 0; mm < 2; mm++) {
                    asm volatile(
                        "mma.sync.aligned.m16n8k8.row.col.f32.tf32.tf32.f32 "
                        "{%0,%1,%2,%3}, {%4,%5,%6,%7}, {%8,%9}, {%0,%1,%2,%3};"
                        : "+f"(c[mm][nn][0]), "+f"(c[mm][nn][1]),
                          "+f"(c[mm][nn][2]), "+f"(c[mm][nn][3])
                        : "r"(__float_as_uint(a[mm][0])), "r"(__float_as_uint(a[mm][1])),
                          "r"(__float_as_uint(a[mm][2])), "r"(__float_as_uint(a[mm][3])),
                          "r"(__float_as_uint(b0)), "r"(__float_as_uint(b1)));
                }
            }
        }
        __syncthreads();
    }

    if (!do_epi) {
        #pragma unroll
        for (int mm = 0; mm < 2; mm++) {
            int row0 = rowBase + wm * 32 + mm * 16 + g;
            #pragma unroll
            for (int nn = 0; nn < 8; nn++) {
                int col = colBase + wn * 64 + nn * 8 + q * 2;
                *(float2*)&Cout[(size_t)row0 * Ncols + col] =
                    make_float2(c[mm][nn][0], c[mm][nn][1]);
                *(float2*)&Cout[(size_t)(row0 + 8) * Ncols + col] =
                    make_float2(c[mm][nn][2], c[mm][nn][3]);
            }
        }
    } else {
        const float b0v = bias[0];
        const size_t xoff = (size_t)NN * NN;
        #pragma unroll
        for (int mm = 0; mm < 2; mm++) {
            int row0 = rowBase + wm * 32 + mm * 16 + g;
            int row1 = row0 + 8;
            float ll0 = g_linl[row0] + b0v;
            float ll1 = g_linl[row1] + b0v;
            #pragma unroll
            for (int nn = 0; nn < 8; nn++) {
                int col = colBase + wn * 64 + nn * 8 + q * 2;
                float lr0 = g_linr[col];
                float lr1 = g_linr[col + 1];
                float v00 = c[mm][nn][0] + ll0 + lr0; v00 = v00 > 0.f ? v00 : 0.f;
                float v01 = c[mm][nn][1] + ll0 + lr1; v01 = v01 > 0.f ? v01 : 0.f;
                float v10 = c[mm][nn][2] + ll1 + lr0; v10 = v10 > 0.f ? v10 : 0.f;
                float v11 = c[mm][nn][3] + ll1 + lr1; v11 = v11 > 0.f ? v11 : 0.f;
                size_t b0i = (size_t)row0 * NN + col;
                size_t b1i = (size_t)row1 * NN + col;
                if (write_x_half) {
                    *(float2*)&Cout[xoff + b0i] = make_float2(v00, v01);
                    *(float2*)&Cout[xoff + b1i] = make_float2(v10, v11);
                }
                int2 m0 = *(const int2*)&mask[b0i];
                int2 m1 = *(const int2*)&mask[b1i];
                *(float2*)&Cout[b0i] = make_float2(m0.x ? v00 : 0.f, m0.y ? v01 : 0.f);
                *(float2*)&Cout[b1i] = make_float2(m1.x ? v10 : 0.f, m1.y ? v11 : 0.f);
            }
        }
    }
}

// ---------------------------------------------------------------------------
extern "C" void kernel_launch(void* const* d_in, const int* in_sizes, int n_in,
                              void* d_out, int out_size)
{
    const float* xl     = (const float*)d_in[0];
    const float* xr     = (const float*)d_in[1];
    const int*   mask   = (const int*)d_in[2];
    const float* matrix = (const float*)d_in[3];
    const float* bias   = (const float*)d_in[4];
    const float* wl     = (const float*)d_in[5];
    const float* bl     = (const float*)d_in[6];
    const float* wr     = (const float*)d_in[7];
    const float* br     = (const float*)d_in[8];
    float* out = (float*)d_out;

    int write_x_half = (out_size >= 2 * NN * NN) ? 1 : 0;

    // 1) linear terms + M^T (independent)
    lin_kernel<<<1024, 256>>>(xl, xr, wl, bl, wr, br);
    transpose_kernel<<<dim3(32, 32), dim3(32, 8)>>>(matrix);

    float* xm;
    cudaGetSymbolAddress((void**)&xm, g_xm);
    float* mt;
    cudaGetSymbolAddress((void**)&mt, g_mt);

    // 2) XM = x_l @ M  (as NT with M^T)
    {
        dim3 grid(DD / BN, NN / BM);   // (8, 32)
        gemm_tf32<<<grid, 256>>>(xl, mt, DD, xm, nullptr, nullptr, 0, 0);
    }

    // 3) S = XM @ x_r^T + epilogue
    {
        dim3 grid(NN / BN, NN / BM);   // (32, 32)
        gemm_tf32<<<grid, 256>>>(xm, xr, NN, out, mask, bias, 1, write_x_half);
    }
}

// round 5
// speedup vs baseline: 2.1074x; 1.0062x over previous
#include <cuda_runtime.h>
#include <cstdint>

#define NN 4096
#define DD 1024
#define BM 128
#define BN 128
#define BK 32
#define PAD 36   // smem row stride (floats): bank = 4*r + c -> conflict-free frags

// Scratch (allocation-free: __device__ globals)
__device__ float g_xm[NN * DD];   // x_l @ M  (16 MB)
__device__ float g_mt[DD * DD];   // M^T      (4 MB)
__device__ float g_linl[NN];
__device__ float g_linr[NN];

__device__ __forceinline__ float tf32r(float x) {
    uint32_t y;
    asm("cvt.rna.tf32.f32 %0, %1;" : "=r"(y) : "f"(x));
    return __uint_as_float(y);
}

// ---------------------------------------------------------------------------
// lin terms: warp per row, float4 + shfl. Grid: 1024 blocks x 256.
// ---------------------------------------------------------------------------
__global__ __launch_bounds__(256) void lin_kernel(
    const float* __restrict__ xl, const float* __restrict__ xr,
    const float* __restrict__ wl, const float* __restrict__ bl,
    const float* __restrict__ wr, const float* __restrict__ br)
{
    int gw   = (blockIdx.x * 256 + threadIdx.x) >> 5;
    int lane = threadIdx.x & 31;
    int right = gw >= NN;
    int row = right ? gw - NN : gw;
    const float* x = right ? xr : xl;
    const float* w = right ? wr : wl;
    const float4* xv = (const float4*)(x + (size_t)row * DD);
    const float4* wv = (const float4*)w;
    float s = 0.f;
    #pragma unroll
    for (int i = 0; i < 8; i++) {
        float4 a = xv[lane + i * 32];
        float4 b = wv[lane + i * 32];
        s += a.x * b.x + a.y * b.y + a.z * b.z + a.w * b.w;
    }
    #pragma unroll
    for (int o = 16; o; o >>= 1) s += __shfl_xor_sync(0xffffffffu, s, o);
    if (lane == 0) {
        if (right) g_linr[row] = s + br[0];
        else       g_linl[row] = s + bl[0];
    }
}

// ---------------------------------------------------------------------------
// M[k][n] -> g_mt[n][k]. Grid (32,32), block (32,8).
// ---------------------------------------------------------------------------
__global__ void transpose_kernel(const float* __restrict__ in)
{
    __shared__ float tile[32][33];
    int x = blockIdx.x * 32 + threadIdx.x;
    int y = blockIdx.y * 32 + threadIdx.y;
    #pragma unroll
    for (int i = 0; i < 32; i += 8)
        tile[threadIdx.y + i][threadIdx.x] = in[(size_t)(y + i) * DD + x];
    __syncthreads();
    x = blockIdx.y * 32 + threadIdx.x;
    y = blockIdx.x * 32 + threadIdx.y;
    #pragma unroll
    for (int i = 0; i < 32; i += 8)
        g_mt[(size_t)(y + i) * DD + x] = tile[threadIdx.x][threadIdx.y + i];
}

// ---------------------------------------------------------------------------
// tf32 NT GEMM: C[m,n] = sum_k A[m,k] * B[n,k], K = 1024.
// A row-major lda=1024, B row-major ldb=1024 (K contiguous in both).
// Block 128x128x32, 8 warps (4 M x 2 N), warp tile 32x64, mma m16n8k8.
// do_epi=0: raw store to Cout (ld = Ncols).
// do_epi=1: v=relu(c+bias+linl[m]+linr[n]); out[m,n]=mask?v:0; out2[m,n]=v.
// ---------------------------------------------------------------------------
__global__ __launch_bounds__(256) void gemm_tf32(
    const float* __restrict__ A, const float* __restrict__ B,
    int Ncols, float* __restrict__ Cout,
    const int* __restrict__ mask, const float* __restrict__ bias,
    int do_epi, int write_x_half)
{
    __shared__ float As[BM][PAD];
    __shared__ float Bs[BN][PAD];

    const int t    = threadIdx.x;
    const int lane = t & 31;
    const int wid  = t >> 5;
    const int wm   = wid >> 1;      // 0..3
    const int wn   = wid & 1;       // 0..1
    const int g    = lane >> 2;     // 0..7
    const int q    = lane & 3;      // 0..3

    const int rowBase = blockIdx.y * BM;
    const int colBase = blockIdx.x * BN;

    float c[2][8][4];
    #pragma unroll
    for (int mm = 0; mm < 2; mm++)
        #pragma unroll
        for (int nn = 0; nn < 8; nn++)
            #pragma unroll
            for (int r = 0; r < 4; r++) c[mm][nn][r] = 0.f;

    for (int k0 = 0; k0 < DD; k0 += BK) {
        // stage tiles (tf32-rounded): 1024 float4 each, 4 per thread
        #pragma unroll
        for (int i = 0; i < 4; i++) {
            int idx = i * 256 + t;
            int r   = idx >> 3;
            int k4  = (idx & 7) * 4;
            float4 av = *(const float4*)&A[(size_t)(rowBase + r) * DD + k0 + k4];
            As[r][k4 + 0] = tf32r(av.x);
            As[r][k4 + 1] = tf32r(av.y);
            As[r][k4 + 2] = tf32r(av.z);
            As[r][k4 + 3] = tf32r(av.w);
            float4 bv = *(const float4*)&B[(size_t)(colBase + r) * DD + k0 + k4];
            Bs[r][k4 + 0] = tf32r(bv.x);
            Bs[r][k4 + 1] = tf32r(bv.y);
            Bs[r][k4 + 2] = tf32r(bv.z);
            Bs[r][k4 + 3] = tf32r(bv.w);
        }
        __syncthreads();

        #pragma unroll
        for (int ks = 0; ks < 4; ks++) {
            int kb = ks * 8;
            float a[2][4];
            #pragma unroll
            for (int mm = 0; mm < 2; mm++) {
                int r = wm * 32 + mm * 16 + g;
                a[mm][0] = As[r][kb + q];
                a[mm][1] = As[r + 8][kb + q];
                a[mm][2] = As[r][kb + q + 4];
                a[mm][3] = As[r + 8][kb + q + 4];
            }
            #pragma unroll
            for (int nn = 0; nn < 8; nn++) {
                int n = wn * 64 + nn * 8 + g;
                float b0 = Bs[n][kb + q];
                float b1 = Bs[n][kb + q + 4];
                #pragma unroll
                for (int mm = 0; mm < 2; mm++) {
                    asm volatile(
                        "mma.sync.aligned.m16n8k8.row.col.f32.tf32.tf32.f32 "
                        "{%0,%1,%2,%3}, {%4,%5,%6,%7}, {%8,%9}, {%0,%1,%2,%3};"
                        : "+f"(c[mm][nn][0]), "+f"(c[mm][nn][1]),
                          "+f"(c[mm][nn][2]), "+f"(c[mm][nn][3])
                        : "r"(__float_as_uint(a[mm][0])), "r"(__float_as_uint(a[mm][1])),
                          "r"(__float_as_uint(a[mm][2])), "r"(__float_as_uint(a[mm][3])),
                          "r"(__float_as_uint(b0)), "r"(__float_as_uint(b1)));
                }
            }
        }
        __syncthreads();
    }

    if (!do_epi) {
        #pragma unroll
        for (int mm = 0; mm < 2; mm++) {
            int row0 = rowBase + wm * 32 + mm * 16 + g;
            #pragma unroll
            for (int nn = 0; nn < 8; nn++) {
                int col = colBase + wn * 64 + nn * 8 + q * 2;
                *(float2*)&Cout[(size_t)row0 * Ncols + col] =
                    make_float2(c[mm][nn][0], c[mm][nn][1]);
                *(float2*)&Cout[(size_t)(row0 + 8) * Ncols + col] =
                    make_float2(c[mm][nn][2], c[mm][nn][3]);
            }
        }
    } else {
        const float b0v = bias[0];
        const size_t xoff = (size_t)NN * NN;
        #pragma unroll
        for (int mm = 0; mm < 2; mm++) {
            int row0 = rowBase + wm * 32 + mm * 16 + g;
            int row1 = row0 + 8;
            float ll0 = g_linl[row0] + b0v;
            float ll1 = g_linl[row1] + b0v;
            #pragma unroll
            for (int nn = 0; nn < 8; nn++) {
                int col = colBase + wn * 64 + nn * 8 + q * 2;
                float lr0 = g_linr[col];
                float lr1 = g_linr[col + 1];
                float v00 = c[mm][nn][0] + ll0 + lr0; v00 = v00 > 0.f ? v00 : 0.f;
                float v01 = c[mm][nn][1] + ll0 + lr1; v01 = v01 > 0.f ? v01 : 0.f;
                float v10 = c[mm][nn][2] + ll1 + lr0; v10 = v10 > 0.f ? v10 : 0.f;
                float v11 = c[mm][nn][3] + ll1 + lr1; v11 = v11 > 0.f ? v11 : 0.f;
                size_t b0i = (size_t)row0 * NN + col;
                size_t b1i = (size_t)row1 * NN + col;
                if (write_x_half) {
                    *(float2*)&Cout[xoff + b0i] = make_float2(v00, v01);
                    *(float2*)&Cout[xoff + b1i] = make_float2(v10, v11);
                }
                int2 m0 = *(const int2*)&mask[b0i];
                int2 m1 = *(const int2*)&mask[b1i];
                *(float2*)&Cout[b0i] = make_float2(m0.x ? v00 : 0.f, m0.y ? v01 : 0.f);
                *(float2*)&Cout[b1i] = make_float2(m1.x ? v10 : 0.f, m1.y ? v11 : 0.f);
            }
        }
    }
}

// ---------------------------------------------------------------------------
extern "C" void kernel_launch(void* const* d_in, const int* in_sizes, int n_in,
                              void* d_out, int out_size)
{
    const float* xl     = (const float*)d_in[0];
    const float* xr     = (const float*)d_in[1];
    const int*   mask   = (const int*)d_in[2];
    const float* matrix = (const float*)d_in[3];
    const float* bias   = (const float*)d_in[4];
    const float* wl     = (const float*)d_in[5];
    const float* bl     = (const float*)d_in[6];
    const float* wr     = (const float*)d_in[7];
    const float* br     = (const float*)d_in[8];
    float* out = (float*)d_out;

    int write_x_half = (out_size >= 2 * NN * NN) ? 1 : 0;

    // 1) linear terms + M^T (independent)
    lin_kernel<<<1024, 256>>>(xl, xr, wl, bl, wr, br);
    transpose_kernel<<<dim3(32, 32), dim3(32, 8)>>>(matrix);

    float* xm;
    cudaGetSymbolAddress((void**)&xm, g_xm);
    float* mt;
    cudaGetSymbolAddress((void**)&mt, g_mt);

    // 2) XM = x_l @ M  (as NT with M^T)
    {
        dim3 grid(DD / BN, NN / BM);   // (8, 32)
        gemm_tf32<<<grid, 256>>>(xl, mt, DD, xm, nullptr, nullptr, 0, 0);
    }

    // 3) S = XM @ x_r^T + epilogue
    {
        dim3 grid(NN / BN, NN / BM);   // (32, 32)
        gemm_tf32<<<grid, 256>>>(xm, xr, NN, out, mask, bias, 1, write_x_half);
    }
}

// round 6
// speedup vs baseline: 3.6348x; 1.7248x over previous
#include <cuda_runtime.h>
#include <cstdint>

#define NN 4096
#define DD 1024
#define BM 128
#define BN 128
#define BK 32
#define PAD 36              // smem row stride (floats): conflict-free frag LDS
#define STAGE_F ((BM + BN) * PAD)          // floats per stage (9216)
#define SMEM_BYTES (2 * STAGE_F * 4)       // 73728 B

// Scratch (allocation-free: __device__ globals)
__device__ float g_xm[NN * DD];    // x_l @ M (tf32-rounded)  16 MB
__device__ float g_mt[DD * DD];    // M^T (tf32-rounded)       4 MB
__device__ float g_xlr[NN * DD];   // tf32(x_l)               16 MB
__device__ float g_xrr[NN * DD];   // tf32(x_r)               16 MB
__device__ float g_linl[NN];
__device__ float g_linr[NN];

__device__ __forceinline__ float tf32r(float x) {
    uint32_t y;
    asm("cvt.rna.tf32.f32 %0, %1;" : "=r"(y) : "f"(x));
    return __uint_as_float(y);
}
__device__ __forceinline__ void cp16(uint32_t dst, const void* src) {
    asm volatile("cp.async.cg.shared.global [%0], [%1], 16;" :: "r"(dst), "l"(src));
}

// ---------------------------------------------------------------------------
// Round fp32 -> tf32 bit pattern, float4 grid-stride.
// ---------------------------------------------------------------------------
__global__ __launch_bounds__(256) void round_kernel(
    const float4* __restrict__ in, float4* __restrict__ out, int n4)
{
    int i = blockIdx.x * 256 + threadIdx.x;
    int stride = gridDim.x * 256;
    for (; i < n4; i += stride) {
        float4 v = in[i];
        out[i] = make_float4(tf32r(v.x), tf32r(v.y), tf32r(v.z), tf32r(v.w));
    }
}

// ---------------------------------------------------------------------------
// lin terms: warp per row, float4 + shfl (exact fp32).
// ---------------------------------------------------------------------------
__global__ __launch_bounds__(256) void lin_kernel(
    const float* __restrict__ xl, const float* __restrict__ xr,
    const float* __restrict__ wl, const float* __restrict__ bl,
    const float* __restrict__ wr, const float* __restrict__ br)
{
    int gw   = (blockIdx.x * 256 + threadIdx.x) >> 5;
    int lane = threadIdx.x & 31;
    int right = gw >= NN;
    int row = right ? gw - NN : gw;
    const float* x = right ? xr : xl;
    const float* w = right ? wr : wl;
    const float4* xv = (const float4*)(x + (size_t)row * DD);
    const float4* wv = (const float4*)w;
    float s = 0.f;
    #pragma unroll
    for (int i = 0; i < 8; i++) {
        float4 a = xv[lane + i * 32];
        float4 b = wv[lane + i * 32];
        s += a.x * b.x + a.y * b.y + a.z * b.z + a.w * b.w;
    }
    #pragma unroll
    for (int o = 16; o; o >>= 1) s += __shfl_xor_sync(0xffffffffu, s, o);
    if (lane == 0) {
        if (right) g_linr[row] = s + br[0];
        else       g_linl[row] = s + bl[0];
    }
}

// ---------------------------------------------------------------------------
// M[k][n] -> g_mt[n][k], tf32-rounded. Grid (32,32), block (32,8).
// ---------------------------------------------------------------------------
__global__ void transpose_kernel(const float* __restrict__ in)
{
    __shared__ float tile[32][33];
    int x = blockIdx.x * 32 + threadIdx.x;
    int y = blockIdx.y * 32 + threadIdx.y;
    #pragma unroll
    for (int i = 0; i < 32; i += 8)
        tile[threadIdx.y + i][threadIdx.x] = tf32r(in[(size_t)(y + i) * DD + x]);
    __syncthreads();
    x = blockIdx.y * 32 + threadIdx.x;
    y = blockIdx.x * 32 + threadIdx.y;
    #pragma unroll
    for (int i = 0; i < 32; i += 8)
        g_mt[(size_t)(y + i) * DD + x] = tile[threadIdx.x][threadIdx.y + i];
}

// ---------------------------------------------------------------------------
// tf32 NT GEMM with cp.async 2-stage pipeline.
// C[m,n] = sum_k A[m,k]*B[n,k]; A,B pre-rounded tf32, lda=ldb=1024.
// Block 128x128x32, 8 warps (4Mx2N), warp tile 32x64, mma m16n8k8.
// do_epi=0: store tf32r(acc) (XM for pass 2). do_epi=1: full epilogue.
// ---------------------------------------------------------------------------
__global__ __launch_bounds__(256) void gemm_tf32(
    const float* __restrict__ A, const float* __restrict__ B,
    int Ncols, float* __restrict__ Cout,
    const int* __restrict__ mask, const float* __restrict__ bias,
    int do_epi, int write_x_half)
{
    extern __shared__ float sm[];

    const int t    = threadIdx.x;
    const int lane = t & 31;
    const int wid  = t >> 5;
    const int wm   = wid >> 1;
    const int wn   = wid & 1;
    const int g    = lane >> 2;
    const int q    = lane & 3;

    const int rowBase = blockIdx.y * BM;
    const int colBase = blockIdx.x * BN;

    uint32_t smem_u32;
    {
        uint64_t tmp;
        asm("cvta.to.shared.u64 %0, %1;" : "=l"(tmp) : "l"(sm));
        smem_u32 = (uint32_t)tmp;
    }

    // per-thread copy coords: 4 chunks of 16B for each of A,B per stage
    int cr[4], cc[4];
    #pragma unroll
    for (int i = 0; i < 4; i++) {
        int idx = i * 256 + t;
        cr[i] = idx >> 3;
        cc[i] = (idx & 7) * 4;
    }

    float c[2][8][4];
    #pragma unroll
    for (int mm = 0; mm < 2; mm++)
        #pragma unroll
        for (int nn = 0; nn < 8; nn++)
            #pragma unroll
            for (int r = 0; r < 4; r++) c[mm][nn][r] = 0.f;

    // issue stage-s prefetch of k-tile k0
    auto issue = [&](int k0, int s) {
        uint32_t aBase = smem_u32 + (uint32_t)s * STAGE_F * 4;
        uint32_t bBase = aBase + BM * PAD * 4;
        #pragma unroll
        for (int i = 0; i < 4; i++) {
            cp16(aBase + (cr[i] * PAD + cc[i]) * 4,
                 &A[(size_t)(rowBase + cr[i]) * DD + k0 + cc[i]]);
            cp16(bBase + (cr[i] * PAD + cc[i]) * 4,
                 &B[(size_t)(colBase + cr[i]) * DD + k0 + cc[i]]);
        }
        asm volatile("cp.async.commit_group;");
    };

    issue(0, 0);

    for (int k0 = 0; k0 < DD; k0 += BK) {
        int s = (k0 >> 5) & 1;
        if (k0 + BK < DD) {
            issue(k0 + BK, s ^ 1);
            asm volatile("cp.async.wait_group 1;");
        } else {
            asm volatile("cp.async.wait_group 0;");
        }
        __syncthreads();

        const float* Af = sm + s * STAGE_F;
        const float* Bf = Af + BM * PAD;

        #pragma unroll
        for (int ks = 0; ks < 4; ks++) {
            int kb = ks * 8;
            float a[2][4];
            #pragma unroll
            for (int mm = 0; mm < 2; mm++) {
                int r = wm * 32 + mm * 16 + g;
                a[mm][0] = Af[r * PAD + kb + q];
                a[mm][1] = Af[(r + 8) * PAD + kb + q];
                a[mm][2] = Af[r * PAD + kb + q + 4];
                a[mm][3] = Af[(r + 8) * PAD + kb + q + 4];
            }
            #pragma unroll
            for (int nn = 0; nn < 8; nn++) {
                int n = wn * 64 + nn * 8 + g;
                float b0 = Bf[n * PAD + kb + q];
                float b1 = Bf[n * PAD + kb + q + 4];
                #pragma unroll
                for (int mm = 0; mm < 2; mm++) {
                    asm volatile(
                        "mma.sync.aligned.m16n8k8.row.col.f32.tf32.tf32.f32 "
                        "{%0,%1,%2,%3}, {%4,%5,%6,%7}, {%8,%9}, {%0,%1,%2,%3};"
                        : "+f"(c[mm][nn][0]), "+f"(c[mm][nn][1]),
                          "+f"(c[mm][nn][2]), "+f"(c[mm][nn][3])
                        : "r"(__float_as_uint(a[mm][0])), "r"(__float_as_uint(a[mm][1])),
                          "r"(__float_as_uint(a[mm][2])), "r"(__float_as_uint(a[mm][3])),
                          "r"(__float_as_uint(b0)), "r"(__float_as_uint(b1)));
                }
            }
        }
        __syncthreads();
    }

    if (!do_epi) {
        #pragma unroll
        for (int mm = 0; mm < 2; mm++) {
            int row0 = rowBase + wm * 32 + mm * 16 + g;
            #pragma unroll
            for (int nn = 0; nn < 8; nn++) {
                int col = colBase + wn * 64 + nn * 8 + q * 2;
                *(float2*)&Cout[(size_t)row0 * Ncols + col] =
                    make_float2(tf32r(c[mm][nn][0]), tf32r(c[mm][nn][1]));
                *(float2*)&Cout[(size_t)(row0 + 8) * Ncols + col] =
                    make_float2(tf32r(c[mm][nn][2]), tf32r(c[mm][nn][3]));
            }
        }
    } else {
        const float b0v = bias[0];
        const size_t xoff = (size_t)NN * NN;
        #pragma unroll
        for (int mm = 0; mm < 2; mm++) {
            int row0 = rowBase + wm * 32 + mm * 16 + g;
            int row1 = row0 + 8;
            float ll0 = g_linl[row0] + b0v;
            float ll1 = g_linl[row1] + b0v;
            #pragma unroll
            for (int nn = 0; nn < 8; nn++) {
                int col = colBase + wn * 64 + nn * 8 + q * 2;
                float lr0 = g_linr[col];
                float lr1 = g_linr[col + 1];
                float v00 = c[mm][nn][0] + ll0 + lr0; v00 = v00 > 0.f ? v00 : 0.f;
                float v01 = c[mm][nn][1] + ll0 + lr1; v01 = v01 > 0.f ? v01 : 0.f;
                float v10 = c[mm][nn][2] + ll1 + lr0; v10 = v10 > 0.f ? v10 : 0.f;
                float v11 = c[mm][nn][3] + ll1 + lr1; v11 = v11 > 0.f ? v11 : 0.f;
                size_t b0i = (size_t)row0 * NN + col;
                size_t b1i = (size_t)row1 * NN + col;
                if (write_x_half) {
                    *(float2*)&Cout[xoff + b0i] = make_float2(v00, v01);
                    *(float2*)&Cout[xoff + b1i] = make_float2(v10, v11);
                }
                int2 m0 = *(const int2*)&mask[b0i];
                int2 m1 = *(const int2*)&mask[b1i];
                *(float2*)&Cout[b0i] = make_float2(m0.x ? v00 : 0.f, m0.y ? v01 : 0.f);
                *(float2*)&Cout[b1i] = make_float2(m1.x ? v10 : 0.f, m1.y ? v11 : 0.f);
            }
        }
    }
}

// ---------------------------------------------------------------------------
extern "C" void kernel_launch(void* const* d_in, const int* in_sizes, int n_in,
                              void* d_out, int out_size)
{
    const float* xl     = (const float*)d_in[0];
    const float* xr     = (const float*)d_in[1];
    const int*   mask   = (const int*)d_in[2];
    const float* matrix = (const float*)d_in[3];
    const float* bias   = (const float*)d_in[4];
    const float* wl     = (const float*)d_in[5];
    const float* bl     = (const float*)d_in[6];
    const float* wr     = (const float*)d_in[7];
    const float* br     = (const float*)d_in[8];
    float* out = (float*)d_out;

    int write_x_half = (out_size >= 2 * NN * NN) ? 1 : 0;

    cudaFuncSetAttribute(gemm_tf32,
                         cudaFuncAttributeMaxDynamicSharedMemorySize, SMEM_BYTES);

    float *xm, *mt, *xlr, *xrr;
    cudaGetSymbolAddress((void**)&xm, g_xm);
    cudaGetSymbolAddress((void**)&mt, g_mt);
    cudaGetSymbolAddress((void**)&xlr, g_xlr);
    cudaGetSymbolAddress((void**)&xrr, g_xrr);

    // 1) prep: lin terms (exact), M^T rounded, tf32 copies of x_l/x_r
    lin_kernel<<<1024, 256>>>(xl, xr, wl, bl, wr, br);
    transpose_kernel<<<dim3(32, 32), dim3(32, 8)>>>(matrix);
    round_kernel<<<592, 256>>>((const float4*)xl, (float4*)xlr, NN * DD / 4);
    round_kernel<<<592, 256>>>((const float4*)xr, (float4*)xrr, NN * DD / 4);

    // 2) XM = tf32(x_l) @ M  (NT with rounded M^T), output tf32-rounded
    {
        dim3 grid(DD / BN, NN / BM);   // (8, 32)
        gemm_tf32<<<grid, 256, SMEM_BYTES>>>(xlr, mt, DD, xm,
                                             nullptr, nullptr, 0, 0);
    }

    // 3) S = XM @ tf32(x_r)^T + epilogue
    {
        dim3 grid(NN / BN, NN / BM);   // (32, 32)
        gemm_tf32<<<grid, 256, SMEM_BYTES>>>(xm, xrr, NN, out,
                                             mask, bias, 1, write_x_half);
    }
}

// round 8
// speedup vs baseline: 3.6752x; 1.0111x over previous
#include <cuda_runtime.h>
#include <cstdint>

#define NN 4096
#define DD 1024
#define BM 128
#define BN 128
#define BK 32
#define PAD 36              // smem row stride (floats): conflict-free frag LDS
#define STAGE_F ((BM + BN) * PAD)          // floats per stage (9216)
#define SMEM_BYTES (2 * STAGE_F * 4)       // 73728 B

// Scratch (allocation-free: __device__ globals)
__device__ float g_xm[NN * DD];    // x_l @ M (tf32-rounded)  16 MB
__device__ float g_mt[DD * DD];    // M^T (tf32-rounded)       4 MB
__device__ float g_xlr[NN * DD];   // tf32(x_l)               16 MB
__device__ float g_xrr[NN * DD];   // tf32(x_r)               16 MB
__device__ float g_linl[NN];
__device__ float g_linr[NN];

__device__ __forceinline__ float tf32r(float x) {
    uint32_t y;
    asm("cvt.rna.tf32.f32 %0, %1;" : "=r"(y) : "f"(x));
    return __uint_as_float(y);
}
__device__ __forceinline__ void cp16(uint32_t dst, const void* src) {
    asm volatile("cp.async.cg.shared.global [%0], [%1], 16;" :: "r"(dst), "l"(src));
}

// ---------------------------------------------------------------------------
// Fused prep: rounds x_l and x_r to tf32 copies (grid-stride over both).
// ---------------------------------------------------------------------------
__global__ __launch_bounds__(256) void round2_kernel(
    const float4* __restrict__ a, float4* __restrict__ ao,
    const float4* __restrict__ b, float4* __restrict__ bo, int n4)
{
    int i = blockIdx.x * 256 + threadIdx.x;
    int stride = gridDim.x * 256;
    for (; i < n4; i += stride) {
        float4 v = a[i];
        ao[i] = make_float4(tf32r(v.x), tf32r(v.y), tf32r(v.z), tf32r(v.w));
        float4 w = b[i];
        bo[i] = make_float4(tf32r(w.x), tf32r(w.y), tf32r(w.z), tf32r(w.w));
    }
}

// ---------------------------------------------------------------------------
// lin terms: warp per row, float4 + shfl (exact fp32).
// ---------------------------------------------------------------------------
__global__ __launch_bounds__(256) void lin_kernel(
    const float* __restrict__ xl, const float* __restrict__ xr,
    const float* __restrict__ wl, const float* __restrict__ bl,
    const float* __restrict__ wr, const float* __restrict__ br)
{
    int gw   = (blockIdx.x * 256 + threadIdx.x) >> 5;
    int lane = threadIdx.x & 31;
    int right = gw >= NN;
    int row = right ? gw - NN : gw;
    const float* x = right ? xr : xl;
    const float* w = right ? wr : wl;
    const float4* xv = (const float4*)(x + (size_t)row * DD);
    const float4* wv = (const float4*)w;
    float s = 0.f;
    #pragma unroll
    for (int i = 0; i < 8; i++) {
        float4 a = xv[lane + i * 32];
        float4 b = wv[lane + i * 32];
        s += a.x * b.x + a.y * b.y + a.z * b.z + a.w * b.w;
    }
    #pragma unroll
    for (int o = 16; o; o >>= 1) s += __shfl_xor_sync(0xffffffffu, s, o);
    if (lane == 0) {
        if (right) g_linr[row] = s + br[0];
        else       g_linl[row] = s + bl[0];
    }
}

// ---------------------------------------------------------------------------
// M[k][n] -> g_mt[n][k], tf32-rounded. Grid (32,32), block (32,8).
// ---------------------------------------------------------------------------
__global__ void transpose_kernel(const float* __restrict__ in)
{
    __shared__ float tile[32][33];
    int x = blockIdx.x * 32 + threadIdx.x;
    int y = blockIdx.y * 32 + threadIdx.y;
    #pragma unroll
    for (int i = 0; i < 32; i += 8)
        tile[threadIdx.y + i][threadIdx.x] = tf32r(in[(size_t)(y + i) * DD + x]);
    __syncthreads();
    x = blockIdx.y * 32 + threadIdx.x;
    y = blockIdx.x * 32 + threadIdx.y;
    #pragma unroll
    for (int i = 0; i < 32; i += 8)
        g_mt[(size_t)(y + i) * DD + x] = tile[threadIdx.x][threadIdx.y + i];
}

// ---------------------------------------------------------------------------
// tf32 NT GEMM, cp.async 2-stage + register fragment double-buffering.
// C[m,n] = sum_k A[m,k]*B[n,k]; A,B pre-rounded tf32, lda=ldb=1024.
// Block 128x128x32, 8 warps (4Mx2N), warp tile 32x64, mma m16n8k8.
// ---------------------------------------------------------------------------
__global__ __launch_bounds__(256) void gemm_tf32(
    const float* __restrict__ A, const float* __restrict__ B,
    int Ncols, float* __restrict__ Cout,
    const int* __restrict__ mask, const float* __restrict__ bias,
    int do_epi, int write_x_half)
{
    extern __shared__ float sm[];

    const int t    = threadIdx.x;
    const int lane = t & 31;
    const int wid  = t >> 5;
    const int wm   = wid >> 1;
    const int wn   = wid & 1;
    const int g    = lane >> 2;
    const int q    = lane & 3;

    const int rowBase = blockIdx.y * BM;
    const int colBase = blockIdx.x * BN;

    uint32_t smem_u32;
    {
        uint64_t tmp;
        asm("cvta.to.shared.u64 %0, %1;" : "=l"(tmp) : "l"(sm));
        smem_u32 = (uint32_t)tmp;
    }

    int cr[4], cc[4];
    #pragma unroll
    for (int i = 0; i < 4; i++) {
        int idx = i * 256 + t;
        cr[i] = idx >> 3;
        cc[i] = (idx & 7) * 4;
    }

    float c[2][8][4];
    #pragma unroll
    for (int mm = 0; mm < 2; mm++)
        #pragma unroll
        for (int nn = 0; nn < 8; nn++)
            #pragma unroll
            for (int r = 0; r < 4; r++) c[mm][nn][r] = 0.f;

    auto issue = [&](int k0, int s) {
        uint32_t aBase = smem_u32 + (uint32_t)s * STAGE_F * 4;
        uint32_t bBase = aBase + BM * PAD * 4;
        #pragma unroll
        for (int i = 0; i < 4; i++) {
            cp16(aBase + (cr[i] * PAD + cc[i]) * 4,
                 &A[(size_t)(rowBase + cr[i]) * DD + k0 + cc[i]]);
            cp16(bBase + (cr[i] * PAD + cc[i]) * 4,
                 &B[(size_t)(colBase + cr[i]) * DD + k0 + cc[i]]);
        }
        asm volatile("cp.async.commit_group;");
    };

    issue(0, 0);

    // fragment double buffers
    float a[2][2][4];     // [buf][mm][4]
    float b[2][8][2];     // [buf][nn][2]

    const int ar0 = wm * 32 + g;        // A frag rows: ar0, ar0+8 (mm adds 16)
    const int bn0 = wn * 64 + g;        // B frag rows: bn0 + nn*8

    for (int k0 = 0; k0 < DD; k0 += BK) {
        int s = (k0 >> 5) & 1;
        if (k0 + BK < DD) {
            issue(k0 + BK, s ^ 1);
            asm volatile("cp.async.wait_group 1;");
        } else {
            asm volatile("cp.async.wait_group 0;");
        }
        __syncthreads();

        const float* Af = sm + s * STAGE_F;
        const float* Bf = Af + BM * PAD;

        // preload ks=0 frags into buf 0
        #pragma unroll
        for (int mm = 0; mm < 2; mm++) {
            int r = ar0 + mm * 16;
            a[0][mm][0] = Af[r * PAD + q];
            a[0][mm][1] = Af[(r + 8) * PAD + q];
            a[0][mm][2] = Af[r * PAD + q + 4];
            a[0][mm][3] = Af[(r + 8) * PAD + q + 4];
        }
        #pragma unroll
        for (int nn = 0; nn < 8; nn++) {
            int n = bn0 + nn * 8;
            b[0][nn][0] = Bf[n * PAD + q];
            b[0][nn][1] = Bf[n * PAD + q + 4];
        }

        #pragma unroll
        for (int ks = 0; ks < 4; ks++) {
            int cur = ks & 1;
            int nxt = cur ^ 1;
            if (ks < 3) {
                int kb = (ks + 1) * 8;
                #pragma unroll
                for (int mm = 0; mm < 2; mm++) {
                    int r = ar0 + mm * 16;
                    a[nxt][mm][0] = Af[r * PAD + kb + q];
                    a[nxt][mm][1] = Af[(r + 8) * PAD + kb + q];
                    a[nxt][mm][2] = Af[r * PAD + kb + q + 4];
                    a[nxt][mm][3] = Af[(r + 8) * PAD + kb + q + 4];
                }
                #pragma unroll
                for (int nn = 0; nn < 8; nn++) {
                    int n = bn0 + nn * 8;
                    b[nxt][nn][0] = Bf[n * PAD + kb + q];
                    b[nxt][nn][1] = Bf[n * PAD + kb + q + 4];
                }
            }
            #pragma unroll
            for (int nn = 0; nn < 8; nn++) {
                #pragma unroll
                for (int mm = 0; mm < 2; mm++) {
                    asm volatile(
                        "mma.sync.aligned.m16n8k8.row.col.f32.tf32.tf32.f32 "
                        "{%0,%1,%2,%3}, {%4,%5,%6,%7}, {%8,%9}, {%0,%1,%2,%3};"
                        : "+f"(c[mm][nn][0]), "+f"(c[mm][nn][1]),
                          "+f"(c[mm][nn][2]), "+f"(c[mm][nn][3])
                        : "r"(__float_as_uint(a[cur][mm][0])), "r"(__float_as_uint(a[cur][mm][1])),
                          "r"(__float_as_uint(a[cur][mm][2])), "r"(__float_as_uint(a[cur][mm][3])),
                          "r"(__float_as_uint(b[cur][nn][0])), "r"(__float_as_uint(b[cur][nn][1])));
                }
            }
        }
        __syncthreads();
    }

    if (!do_epi) {
        #pragma unroll
        for (int mm = 0; mm < 2; mm++) {
            int row0 = rowBase + wm * 32 + mm * 16 + g;
            #pragma unroll
            for (int nn = 0; nn < 8; nn++) {
                int col = colBase + wn * 64 + nn * 8 + q * 2;
                *(float2*)&Cout[(size_t)row0 * Ncols + col] =
                    make_float2(tf32r(c[mm][nn][0]), tf32r(c[mm][nn][1]));
                *(float2*)&Cout[(size_t)(row0 + 8) * Ncols + col] =
                    make_float2(tf32r(c[mm][nn][2]), tf32r(c[mm][nn][3]));
            }
        }
    } else {
        const float b0v = bias[0];
        const size_t xoff = (size_t)NN * NN;
        #pragma unroll
        for (int mm = 0; mm < 2; mm++) {
            int row0 = rowBase + wm * 32 + mm * 16 + g;
            int row1 = row0 + 8;
            float ll0 = g_linl[row0] + b0v;
            float ll1 = g_linl[row1] + b0v;
            #pragma unroll
            for (int nn = 0; nn < 8; nn++) {
                int col = colBase + wn * 64 + nn * 8 + q * 2;
                float lr0 = g_linr[col];
                float lr1 = g_linr[col + 1];
                float v00 = c[mm][nn][0] + ll0 + lr0; v00 = v00 > 0.f ? v00 : 0.f;
                float v01 = c[mm][nn][1] + ll0 + lr1; v01 = v01 > 0.f ? v01 : 0.f;
                float v10 = c[mm][nn][2] + ll1 + lr0; v10 = v10 > 0.f ? v10 : 0.f;
                float v11 = c[mm][nn][3] + ll1 + lr1; v11 = v11 > 0.f ? v11 : 0.f;
                size_t b0i = (size_t)row0 * NN + col;
                size_t b1i = (size_t)row1 * NN + col;
                if (write_x_half) {
                    *(float2*)&Cout[xoff + b0i] = make_float2(v00, v01);
                    *(float2*)&Cout[xoff + b1i] = make_float2(v10, v11);
                }
                int2 m0 = *(const int2*)&mask[b0i];
                int2 m1 = *(const int2*)&mask[b1i];
                *(float2*)&Cout[b0i] = make_float2(m0.x ? v00 : 0.f, m0.y ? v01 : 0.f);
                *(float2*)&Cout[b1i] = make_float2(m1.x ? v10 : 0.f, m1.y ? v11 : 0.f);
            }
        }
    }
}

// ---------------------------------------------------------------------------
extern "C" void kernel_launch(void* const* d_in, const int* in_sizes, int n_in,
                              void* d_out, int out_size)
{
    const float* xl     = (const float*)d_in[0];
    const float* xr     = (const float*)d_in[1];
    const int*   mask   = (const int*)d_in[2];
    const float* matrix = (const float*)d_in[3];
    const float* bias   = (const float*)d_in[4];
    const float* wl     = (const float*)d_in[5];
    const float* bl     = (const float*)d_in[6];
    const float* wr     = (const float*)d_in[7];
    const float* br     = (const float*)d_in[8];
    float* out = (float*)d_out;

    int write_x_half = (out_size >= 2 * NN * NN) ? 1 : 0;

    cudaFuncSetAttribute(gemm_tf32,
                         cudaFuncAttributeMaxDynamicSharedMemorySize, SMEM_BYTES);

    float *xm, *mt, *xlr, *xrr;
    cudaGetSymbolAddress((void**)&xm, g_xm);
    cudaGetSymbolAddress((void**)&mt, g_mt);
    cudaGetSymbolAddress((void**)&xlr, g_xlr);
    cudaGetSymbolAddress((void**)&xrr, g_xrr);

    // 1) prep: lin terms (exact), M^T rounded, tf32 copies of x_l/x_r
    lin_kernel<<<1024, 256>>>(xl, xr, wl, bl, wr, br);
    transpose_kernel<<<dim3(32, 32), dim3(32, 8)>>>(matrix);
    round2_kernel<<<592, 256>>>((const float4*)xl, (float4*)xlr,
                                (const float4*)xr, (float4*)xrr, NN * DD / 4);

    // 2) XM = tf32(x_l) @ M  (NT with rounded M^T), output tf32-rounded
    {
        dim3 grid(DD / BN, NN / BM);   // (8, 32)
        gemm_tf32<<<grid, 256, SMEM_BYTES>>>(xlr, mt, DD, xm,
                                             nullptr, nullptr, 0, 0);
    }

    // 3) S = XM @ tf32(x_r)^T + epilogue
    {
        dim3 grid(NN / BN, NN / BM);   // (32, 32)
        gemm_tf32<<<grid, 256, SMEM_BYTES>>>(xm, xrr, NN, out,
                                             mask, bias, 1, write_x_half);
    }
}

// round 9
// speedup vs baseline: 4.2675x; 1.1612x over previous
#include <cuda_runtime.h>
#include <cstdint>

#define NN 4096
#define DD 1024
#define BM 128
#define BN 128
#define BK 32
#define NKT (DD / BK)                 // 32 k-tiles
#define TILE_F 4096                   // floats per 128x32 operand tile (16KB)
#define STAGE_F4 2048                 // float4 per stage (A tile + B tile)
#define NSTAGE 3
#define GEMM_SMEM (NSTAGE * STAGE_F4 * 16)   // 98304 B

// Scratch (allocation-free: __device__ globals). All operand buffers are
// stored fragment-packed (tile-blocked [rowTile][kTile][4096]).
__device__ float g_xm[NN * DD];    // XM, A-packed for GEMM2   16 MB
__device__ float g_mt[DD * DD];    // M^T, B-packed for GEMM1   4 MB
__device__ float g_xlr[NN * DD];   // x_l, A-packed for GEMM1  16 MB
__device__ float g_xrr[NN * DD];   // x_r, B-packed for GEMM2  16 MB
__device__ float g_linl[NN];
__device__ float g_linr[NN];

__device__ __forceinline__ float tf32r(float x) {
    uint32_t y;
    asm("cvt.rna.tf32.f32 %0, %1;" : "=r"(y) : "f"(x));
    return __uint_as_float(y);
}
__device__ __forceinline__ void cp16(uint32_t dst, const void* src) {
    asm volatile("cp.async.cg.shared.global [%0], [%1], 16;" :: "r"(dst), "l"(src));
}

// fragment-packed index of element (row, k) inside a 128x32 tile.
// A operand (m16n8k8 row frag): a0=[r][q], a1=[r+8][q], a2=[r][q+4], a3=[r+8][q+4]
__device__ __forceinline__ int apack_inner(int row, int k) {
    int wm = row >> 5, mm = (row >> 4) & 1, sub8 = (row >> 3) & 1, g = row & 7;
    int kstep = k >> 3, half = (k >> 2) & 1, q = k & 3;
    return (((((kstep * 4 + wm) * 2 + mm) * 8 + g) * 4 + q) << 2) + half * 2 + sub8;
}
// B operand (col frag): per (np) float4 = (b0[2np], b1[2np], b0[2np+1], b1[2np+1])
__device__ __forceinline__ int bpack_inner(int row, int k) {
    int wn = row >> 6, np = (row >> 4) & 3, nlo = (row >> 3) & 1, g = row & 7;
    int kstep = k >> 3, half = (k >> 2) & 1, q = k & 3;
    return (((((kstep * 2 + wn) * 4 + np) * 8 + g) * 4 + q) << 2) + nlo * 2 + half;
}

// ---------------------------------------------------------------------------
// lin terms: warp per row, float4 + shfl (exact fp32).
// ---------------------------------------------------------------------------
__global__ __launch_bounds__(256) void lin_kernel(
    const float* __restrict__ xl, const float* __restrict__ xr,
    const float* __restrict__ wl, const float* __restrict__ bl,
    const float* __restrict__ wr, const float* __restrict__ br)
{
    int gw   = (blockIdx.x * 256 + threadIdx.x) >> 5;
    int lane = threadIdx.x & 31;
    int right = gw >= NN;
    int row = right ? gw - NN : gw;
    const float* x = right ? xr : xl;
    const float* w = right ? wr : wl;
    const float4* xv = (const float4*)(x + (size_t)row * DD);
    const float4* wv = (const float4*)w;
    float s = 0.f;
    #pragma unroll
    for (int i = 0; i < 8; i++) {
        float4 a = xv[lane + i * 32];
        float4 b = wv[lane + i * 32];
        s += a.x * b.x + a.y * b.y + a.z * b.z + a.w * b.w;
    }
    #pragma unroll
    for (int o = 16; o; o >>= 1) s += __shfl_xor_sync(0xffffffffu, s, o);
    if (lane == 0) {
        if (right) g_linr[row] = s + br[0];
        else       g_linl[row] = s + bl[0];
    }
}

// ---------------------------------------------------------------------------
// Pack x (row-major [rows,1024]) into A- or B-packed tiles, tf32-rounded.
// Grid: (rows/128, 32). Thread t: row t>>1, k-chunk (t&1)*16.
// ---------------------------------------------------------------------------
template <int APACK>
__global__ __launch_bounds__(256) void pack_kernel(
    const float* __restrict__ src, float* __restrict__ dst)
{
    int t = threadIdx.x;
    int r = t >> 1;
    int kOff = (t & 1) * 16;
    size_t srcBase = (size_t)(blockIdx.x * 128 + r) * DD + blockIdx.y * 32 + kOff;
    float* dTile = dst + ((size_t)blockIdx.x * NKT + blockIdx.y) * TILE_F;
    #pragma unroll
    for (int j = 0; j < 4; j++) {
        float4 v = *(const float4*)&src[srcBase + j * 4];
        int kl = kOff + j * 4;
        float vv[4] = {v.x, v.y, v.z, v.w};
        #pragma unroll
        for (int e = 0; e < 4; e++) {
            int idx = APACK ? apack_inner(r, kl + e) : bpack_inner(r, kl + e);
            dTile[idx] = tf32r(vv[e]);
        }
    }
}

// ---------------------------------------------------------------------------
// Pack M (row-major [1024,1024], k-major source) transposed into B-packed
// g_mt[n][k] = M[k][n]. Grid (8 nTiles, 32 kTiles). Thread: k=t>>3, nOff=(t&7)*16.
// ---------------------------------------------------------------------------
__global__ __launch_bounds__(256) void packT_kernel(
    const float* __restrict__ M, float* __restrict__ dst)
{
    int t = threadIdx.x;
    int k = t >> 3;
    int nOff = (t & 7) * 16;
    size_t srcBase = (size_t)(blockIdx.y * 32 + k) * DD + blockIdx.x * 128 + nOff;
    float* dTile = dst + ((size_t)blockIdx.x * NKT + blockIdx.y) * TILE_F;
    #pragma unroll
    for (int j = 0; j < 4; j++) {
        float4 v = *(const float4*)&M[srcBase + j * 4];
        int nl = nOff + j * 4;
        float vv[4] = {v.x, v.y, v.z, v.w};
        #pragma unroll
        for (int e = 0; e < 4; e++)
            dTile[bpack_inner(nl + e, k)] = tf32r(vv[e]);
    }
}

// ---------------------------------------------------------------------------
// tf32 NT GEMM on fragment-packed operands, 3-stage cp.async pipeline.
// Block 128x128x32, 8 warps (4Mx2N), warp tile 32x64, mma m16n8k8.
// mode 0: store tf32r(acc) A-packed into out (feeds GEMM2).
// mode 1: epilogue bias+lin+relu+mask, row-major out.
// ---------------------------------------------------------------------------
__global__ __launch_bounds__(256, 2) void gemm_tc(
    const float* __restrict__ Apk, const float* __restrict__ Bpk,
    float* __restrict__ out,
    const int* __restrict__ mask, const float* __restrict__ bias,
    int mode, int write_x_half)
{
    extern __shared__ __align__(16) float4 sm4[];

    const int tid  = threadIdx.x;
    const int lane = tid & 31;
    const int wid  = tid >> 5;
    const int wm   = wid >> 1;      // 0..3
    const int wn   = wid & 1;       // 0..1
    const int g    = lane >> 2;
    const int q    = lane & 3;
    const int bx   = blockIdx.x;
    const int by   = blockIdx.y;

    uint32_t smB;
    {
        uint64_t tmp;
        asm("cvta.to.shared.u64 %0, %1;" : "=l"(tmp) : "l"(sm4));
        smB = (uint32_t)tmp;
    }

    const float4* Ag = (const float4*)Apk + (size_t)by * NKT * (TILE_F / 4);
    const float4* Bg = (const float4*)Bpk + (size_t)bx * NKT * (TILE_F / 4);

    auto load_tile = [&](int t) {
        uint32_t d = smB + (uint32_t)(t % NSTAGE) * STAGE_F4 * 16;
        const float4* sa = Ag + (size_t)t * (TILE_F / 4);
        const float4* sb = Bg + (size_t)t * (TILE_F / 4);
        #pragma unroll
        for (int j = 0; j < 4; j++) {
            int i = j * 256 + tid;
            cp16(d + (uint32_t)i * 16, sa + i);
            cp16(d + (uint32_t)(1024 + i) * 16, sb + i);
        }
        asm volatile("cp.async.commit_group;");
    };

    float c[2][8][4];
    #pragma unroll
    for (int mm = 0; mm < 2; mm++)
        #pragma unroll
        for (int nn = 0; nn < 8; nn++)
            #pragma unroll
            for (int r = 0; r < 4; r++) c[mm][nn][r] = 0.f;

    load_tile(0); load_tile(1); load_tile(2);

    for (int t = 0; t < NKT; t++) {
        if      (t < NKT - 2) asm volatile("cp.async.wait_group 2;");
        else if (t == NKT - 2) asm volatile("cp.async.wait_group 1;");
        else                   asm volatile("cp.async.wait_group 0;");
        __syncthreads();

        const float4* Af = sm4 + (t % NSTAGE) * STAGE_F4;
        const float4* Bf = Af + 1024;

        #pragma unroll
        for (int ks = 0; ks < 4; ks++) {
            float4 b4[4];
            #pragma unroll
            for (int np = 0; np < 4; np++)
                b4[np] = Bf[((ks * 2 + wn) * 4 + np) * 32 + lane];
            float4 a0 = Af[((ks * 4 + wm) * 2 + 0) * 32 + lane];
            float4 a1 = Af[((ks * 4 + wm) * 2 + 1) * 32 + lane];

            #pragma unroll
            for (int np = 0; np < 4; np++) {
                #pragma unroll
                for (int o = 0; o < 2; o++) {
                    int nn = np * 2 + o;
                    float bb0 = o ? b4[np].z : b4[np].x;
                    float bb1 = o ? b4[np].w : b4[np].y;
                    asm volatile(
                        "mma.sync.aligned.m16n8k8.row.col.f32.tf32.tf32.f32 "
                        "{%0,%1,%2,%3}, {%4,%5,%6,%7}, {%8,%9}, {%0,%1,%2,%3};"
                        : "+f"(c[0][nn][0]), "+f"(c[0][nn][1]),
                          "+f"(c[0][nn][2]), "+f"(c[0][nn][3])
                        : "r"(__float_as_uint(a0.x)), "r"(__float_as_uint(a0.y)),
                          "r"(__float_as_uint(a0.z)), "r"(__float_as_uint(a0.w)),
                          "r"(__float_as_uint(bb0)), "r"(__float_as_uint(bb1)));
                    asm volatile(
                        "mma.sync.aligned.m16n8k8.row.col.f32.tf32.tf32.f32 "
                        "{%0,%1,%2,%3}, {%4,%5,%6,%7}, {%8,%9}, {%0,%1,%2,%3};"
                        : "+f"(c[1][nn][0]), "+f"(c[1][nn][1]),
                          "+f"(c[1][nn][2]), "+f"(c[1][nn][3])
                        : "r"(__float_as_uint(a1.x)), "r"(__float_as_uint(a1.y)),
                          "r"(__float_as_uint(a1.z)), "r"(__float_as_uint(a1.w)),
                          "r"(__float_as_uint(bb0)), "r"(__float_as_uint(bb1)));
                }
            }
        }
        __syncthreads();
        if (t + NSTAGE < NKT) load_tile(t + NSTAGE);
    }

    if (mode == 0) {
        // store A-packed tf32 for GEMM2: element (rowL, colG) -> tile(by, colG>>5)
        #pragma unroll
        for (int mm = 0; mm < 2; mm++) {
            #pragma unroll
            for (int nn = 0; nn < 8; nn++) {
                int colL = wn * 64 + nn * 8 + q * 2;
                int rowL = wm * 32 + mm * 16 + g;
                size_t tb = ((size_t)by * NKT + bx * 4 + (colL >> 5)) * TILE_F;
                int kl = colL & 31;
                out[tb + apack_inner(rowL,     kl)]     = tf32r(c[mm][nn][0]);
                out[tb + apack_inner(rowL,     kl + 1)] = tf32r(c[mm][nn][1]);
                out[tb + apack_inner(rowL + 8, kl)]     = tf32r(c[mm][nn][2]);
                out[tb + apack_inner(rowL + 8, kl + 1)] = tf32r(c[mm][nn][3]);
            }
        }
    } else {
        const float b0v = bias[0];
        const size_t xoff = (size_t)NN * NN;
        const int rowBase = by * BM;
        const int colBase = bx * BN;
        #pragma unroll
        for (int mm = 0; mm < 2; mm++) {
            int row0 = rowBase + wm * 32 + mm * 16 + g;
            int row1 = row0 + 8;
            float ll0 = g_linl[row0] + b0v;
            float ll1 = g_linl[row1] + b0v;
            #pragma unroll
            for (int nn = 0; nn < 8; nn++) {
                int col = colBase + wn * 64 + nn * 8 + q * 2;
                float lr0 = g_linr[col];
                float lr1 = g_linr[col + 1];
                float v00 = c[mm][nn][0] + ll0 + lr0; v00 = v00 > 0.f ? v00 : 0.f;
                float v01 = c[mm][nn][1] + ll0 + lr1; v01 = v01 > 0.f ? v01 : 0.f;
                float v10 = c[mm][nn][2] + ll1 + lr0; v10 = v10 > 0.f ? v10 : 0.f;
                float v11 = c[mm][nn][3] + ll1 + lr1; v11 = v11 > 0.f ? v11 : 0.f;
                size_t b0i = (size_t)row0 * NN + col;
                size_t b1i = (size_t)row1 * NN + col;
                if (write_x_half) {
                    *(float2*)&out[xoff + b0i] = make_float2(v00, v01);
                    *(float2*)&out[xoff + b1i] = make_float2(v10, v11);
                }
                int2 m0 = *(const int2*)&mask[b0i];
                int2 m1 = *(const int2*)&mask[b1i];
                *(float2*)&out[b0i] = make_float2(m0.x ? v00 : 0.f, m0.y ? v01 : 0.f);
                *(float2*)&out[b1i] = make_float2(m1.x ? v10 : 0.f, m1.y ? v11 : 0.f);
            }
        }
    }
}

// ---------------------------------------------------------------------------
extern "C" void kernel_launch(void* const* d_in, const int* in_sizes, int n_in,
                              void* d_out, int out_size)
{
    const float* xl     = (const float*)d_in[0];
    const float* xr     = (const float*)d_in[1];
    const int*   mask   = (const int*)d_in[2];
    const float* matrix = (const float*)d_in[3];
    const float* bias   = (const float*)d_in[4];
    const float* wl     = (const float*)d_in[5];
    const float* bl     = (const float*)d_in[6];
    const float* wr     = (const float*)d_in[7];
    const float* br     = (const float*)d_in[8];
    float* out = (float*)d_out;

    int write_x_half = (out_size >= 2 * NN * NN) ? 1 : 0;

    cudaFuncSetAttribute(gemm_tc,
                         cudaFuncAttributeMaxDynamicSharedMemorySize, GEMM_SMEM);

    float *xm, *mt, *xlr, *xrr;
    cudaGetSymbolAddress((void**)&xm, g_xm);
    cudaGetSymbolAddress((void**)&mt, g_mt);
    cudaGetSymbolAddress((void**)&xlr, g_xlr);
    cudaGetSymbolAddress((void**)&xrr, g_xrr);

    // 1) prep: lin terms (exact), packed tf32 operands
    lin_kernel<<<1024, 256>>>(xl, xr, wl, bl, wr, br);
    pack_kernel<1><<<dim3(NN / 128, NKT), 256>>>(xl, xlr);   // A-packed x_l
    pack_kernel<0><<<dim3(NN / 128, NKT), 256>>>(xr, xrr);   // B-packed x_r
    packT_kernel<<<dim3(DD / 128, NKT), 256>>>(matrix, mt);  // B-packed M^T

    // 2) XM = tf32(x_l) @ M -> A-packed g_xm
    gemm_tc<<<dim3(DD / BN, NN / BM), 256, GEMM_SMEM>>>(
        xlr, mt, xm, nullptr, nullptr, 0, 0);

    // 3) S = XM @ tf32(x_r)^T + epilogue
    gemm_tc<<<dim3(NN / BN, NN / BM), 256, GEMM_SMEM>>>(
        xm, xrr, out, mask, bias, 1, write_x_half);
}

// round 10
// speedup vs baseline: 4.9614x; 1.1626x over previous
#include <cuda_runtime.h>
#include <cstdint>

#define NN 4096
#define DD 1024
#define BM 128
#define BN 128
#define BK 32
#define NKT (DD / BK)                 // 32 k-tiles
#define TILE_F 4096                   // floats per 128x32 operand tile (16KB)
#define TILE_B 16384                  // bytes per operand tile
#define STAGE_B (2 * TILE_B)          // 32 KB per stage (A + B)
#define NSTAGE 3
#define GEMM_SMEM (NSTAGE * STAGE_B)  // 98304 B

// Scratch (allocation-free: __device__ globals). All operand buffers are
// stored fragment-packed (tile-blocked [rowTile][kTile][4096]).
__device__ float g_xm[NN * DD];    // XM, A-packed for GEMM2   16 MB
__device__ float g_mt[DD * DD];    // M^T, B-packed for GEMM1   4 MB
__device__ float g_xlr[NN * DD];   // x_l, A-packed for GEMM1  16 MB
__device__ float g_xrr[NN * DD];   // x_r, B-packed for GEMM2  16 MB
__device__ float g_linl[NN];
__device__ float g_linr[NN];

__device__ __forceinline__ float tf32r(float x) {
    uint32_t y;
    asm("cvt.rna.tf32.f32 %0, %1;" : "=r"(y) : "f"(x));
    return __uint_as_float(y);
}
__device__ __forceinline__ uint32_t smaddr(const void* p) {
    uint64_t t;
    asm("cvta.to.shared.u64 %0, %1;" : "=l"(t) : "l"(p));
    return (uint32_t)t;
}
__device__ __forceinline__ void mbar_wait(uint32_t mbar, uint32_t parity) {
    asm volatile(
        "{\n\t.reg .pred P;\n\t"
        "WL_%=:\n\t"
        "mbarrier.try_wait.parity.acquire.cta.shared::cta.b64 P, [%0], %1, 0x989680;\n\t"
        "@P bra.uni WD_%=;\n\t"
        "bra.uni WL_%=;\n\t"
        "WD_%=:\n\t}"
        :: "r"(mbar), "r"(parity) : "memory");
}
__device__ __forceinline__ void bulk_cp(uint32_t dst, const void* src,
                                        uint32_t bytes, uint32_t mbar) {
    asm volatile(
        "cp.async.bulk.shared::cluster.global.mbarrier::complete_tx::bytes "
        "[%0], [%1], %2, [%3];"
        :: "r"(dst), "l"(src), "r"(bytes), "r"(mbar) : "memory");
}

// fragment-packed index of element (row, k) inside a 128x32 tile.
__device__ __forceinline__ int apack_inner(int row, int k) {
    int wm = row >> 5, mm = (row >> 4) & 1, sub8 = (row >> 3) & 1, g = row & 7;
    int kstep = k >> 3, half = (k >> 2) & 1, q = k & 3;
    return (((((kstep * 4 + wm) * 2 + mm) * 8 + g) * 4 + q) << 2) + half * 2 + sub8;
}
__device__ __forceinline__ int bpack_inner(int row, int k) {
    int wn = row >> 6, np = (row >> 4) & 3, nlo = (row >> 3) & 1, g = row & 7;
    int kstep = k >> 3, half = (k >> 2) & 1, q = k & 3;
    return (((((kstep * 2 + wn) * 4 + np) * 8 + g) * 4 + q) << 2) + nlo * 2 + half;
}

// ---------------------------------------------------------------------------
// lin terms: warp per row, float4 + shfl (exact fp32).
// ---------------------------------------------------------------------------
__global__ __launch_bounds__(256) void lin_kernel(
    const float* __restrict__ xl, const float* __restrict__ xr,
    const float* __restrict__ wl, const float* __restrict__ bl,
    const float* __restrict__ wr, const float* __restrict__ br)
{
    int gw   = (blockIdx.x * 256 + threadIdx.x) >> 5;
    int lane = threadIdx.x & 31;
    int right = gw >= NN;
    int row = right ? gw - NN : gw;
    const float* x = right ? xr : xl;
    const float* w = right ? wr : wl;
    const float4* xv = (const float4*)(x + (size_t)row * DD);
    const float4* wv = (const float4*)w;
    float s = 0.f;
    #pragma unroll
    for (int i = 0; i < 8; i++) {
        float4 a = xv[lane + i * 32];
        float4 b = wv[lane + i * 32];
        s += a.x * b.x + a.y * b.y + a.z * b.z + a.w * b.w;
    }
    #pragma unroll
    for (int o = 16; o; o >>= 1) s += __shfl_xor_sync(0xffffffffu, s, o);
    if (lane == 0) {
        if (right) g_linr[row] = s + br[0];
        else       g_linl[row] = s + bl[0];
    }
}

// ---------------------------------------------------------------------------
// Pack x (row-major [rows,1024]) into A- or B-packed tiles, tf32-rounded.
// ---------------------------------------------------------------------------
template <int APACK>
__global__ __launch_bounds__(256) void pack_kernel(
    const float* __restrict__ src, float* __restrict__ dst)
{
    int t = threadIdx.x;
    int r = t >> 1;
    int kOff = (t & 1) * 16;
    size_t srcBase = (size_t)(blockIdx.x * 128 + r) * DD + blockIdx.y * 32 + kOff;
    float* dTile = dst + ((size_t)blockIdx.x * NKT + blockIdx.y) * TILE_F;
    #pragma unroll
    for (int j = 0; j < 4; j++) {
        float4 v = *(const float4*)&src[srcBase + j * 4];
        int kl = kOff + j * 4;
        float vv[4] = {v.x, v.y, v.z, v.w};
        #pragma unroll
        for (int e = 0; e < 4; e++) {
            int idx = APACK ? apack_inner(r, kl + e) : bpack_inner(r, kl + e);
            dTile[idx] = tf32r(vv[e]);
        }
    }
}

// ---------------------------------------------------------------------------
// Pack M transposed into B-packed: g_mt[n][k] = M[k][n].
// ---------------------------------------------------------------------------
__global__ __launch_bounds__(256) void packT_kernel(
    const float* __restrict__ M, float* __restrict__ dst)
{
    int t = threadIdx.x;
    int k = t >> 3;
    int nOff = (t & 7) * 16;
    size_t srcBase = (size_t)(blockIdx.y * 32 + k) * DD + blockIdx.x * 128 + nOff;
    float* dTile = dst + ((size_t)blockIdx.x * NKT + blockIdx.y) * TILE_F;
    #pragma unroll
    for (int j = 0; j < 4; j++) {
        float4 v = *(const float4*)&M[srcBase + j * 4];
        int nl = nOff + j * 4;
        float vv[4] = {v.x, v.y, v.z, v.w};
        #pragma unroll
        for (int e = 0; e < 4; e++)
            dTile[bpack_inner(nl + e, k)] = tf32r(vv[e]);
    }
}

// ---------------------------------------------------------------------------
// tf32 NT GEMM on fragment-packed operands.
// cp.async.bulk + mbarrier warp-asynchronous 3-stage pipeline (no syncthreads
// in the mainloop). Block 128x128x32, 8 warps (4Mx2N), mma m16n8k8.
// ---------------------------------------------------------------------------
__global__ __launch_bounds__(256, 2) void gemm_tc(
    const float* __restrict__ Apk, const float* __restrict__ Bpk,
    float* __restrict__ out,
    const int* __restrict__ mask, const float* __restrict__ bias,
    int mode, int write_x_half)
{
    extern __shared__ __align__(128) float4 sm4[];
    __shared__ __align__(8) uint64_t s_full[NSTAGE];
    __shared__ __align__(8) uint64_t s_empty[NSTAGE];

    const int tid  = threadIdx.x;
    const int lane = tid & 31;
    const int wid  = tid >> 5;
    const int wm   = wid >> 1;
    const int wn   = wid & 1;
    const int g    = lane >> 2;
    const int q    = lane & 3;
    const int bx   = blockIdx.x;
    const int by   = blockIdx.y;

    const uint32_t smB    = smaddr(sm4);
    const uint32_t fullB  = smaddr(&s_full[0]);
    const uint32_t emptyB = smaddr(&s_empty[0]);

    if (tid == 0) {
        #pragma unroll
        for (int s = 0; s < NSTAGE; s++) {
            asm volatile("mbarrier.init.shared.b64 [%0], 1;"
                         :: "r"(fullB + 8u * s) : "memory");
            asm volatile("mbarrier.init.shared.b64 [%0], 8;"
                         :: "r"(emptyB + 8u * s) : "memory");
        }
    }
    __syncthreads();

    const char* Ag = (const char*)Apk + (size_t)by * NKT * TILE_B;
    const char* Bg = (const char*)Bpk + (size_t)bx * NKT * TILE_B;

    auto issue = [&](int u) {
        int s2 = u % NSTAGE;
        uint32_t fb = fullB + 8u * s2;
        asm volatile("mbarrier.arrive.expect_tx.shared.b64 _, [%0], %1;"
                     :: "r"(fb), "r"((uint32_t)STAGE_B) : "memory");
        uint32_t d = smB + (uint32_t)s2 * STAGE_B;
        bulk_cp(d,          Ag + (size_t)u * TILE_B, TILE_B, fb);
        bulk_cp(d + TILE_B, Bg + (size_t)u * TILE_B, TILE_B, fb);
    };

    if (tid == 0) { issue(0); issue(1); }

    float c[2][8][4];
    #pragma unroll
    for (int mm = 0; mm < 2; mm++)
        #pragma unroll
        for (int nn = 0; nn < 8; nn++)
            #pragma unroll
            for (int r = 0; r < 4; r++) c[mm][nn][r] = 0.f;

    for (int t = 0; t < NKT; t++) {
        int s = t % NSTAGE;
        if (tid == 0 && t + 2 < NKT) {
            int u = t + 2;
            if (u >= NSTAGE)
                mbar_wait(emptyB + 8u * (u % NSTAGE), (u / NSTAGE - 1) & 1);
            issue(u);
        }
        mbar_wait(fullB + 8u * s, (t / NSTAGE) & 1);

        const float4* Af = sm4 + s * (STAGE_B / 16);
        const float4* Bf = Af + (TILE_B / 16);

        #pragma unroll
        for (int ks = 0; ks < 4; ks++) {
            float4 b4[4];
            #pragma unroll
            for (int np = 0; np < 4; np++)
                b4[np] = Bf[((ks * 2 + wn) * 4 + np) * 32 + lane];
            float4 a0 = Af[((ks * 4 + wm) * 2 + 0) * 32 + lane];
            float4 a1 = Af[((ks * 4 + wm) * 2 + 1) * 32 + lane];

            #pragma unroll
            for (int np = 0; np < 4; np++) {
                #pragma unroll
                for (int o = 0; o < 2; o++) {
                    int nn = np * 2 + o;
                    float bb0 = o ? b4[np].z : b4[np].x;
                    float bb1 = o ? b4[np].w : b4[np].y;
                    asm volatile(
                        "mma.sync.aligned.m16n8k8.row.col.f32.tf32.tf32.f32 "
                        "{%0,%1,%2,%3}, {%4,%5,%6,%7}, {%8,%9}, {%0,%1,%2,%3};"
                        : "+f"(c[0][nn][0]), "+f"(c[0][nn][1]),
                          "+f"(c[0][nn][2]), "+f"(c[0][nn][3])
                        : "r"(__float_as_uint(a0.x)), "r"(__float_as_uint(a0.y)),
                          "r"(__float_as_uint(a0.z)), "r"(__float_as_uint(a0.w)),
                          "r"(__float_as_uint(bb0)), "r"(__float_as_uint(bb1)));
                    asm volatile(
                        "mma.sync.aligned.m16n8k8.row.col.f32.tf32.tf32.f32 "
                        "{%0,%1,%2,%3}, {%4,%5,%6,%7}, {%8,%9}, {%0,%1,%2,%3};"
                        : "+f"(c[1][nn][0]), "+f"(c[1][nn][1]),
                          "+f"(c[1][nn][2]), "+f"(c[1][nn][3])
                        : "r"(__float_as_uint(a1.x)), "r"(__float_as_uint(a1.y)),
                          "r"(__float_as_uint(a1.z)), "r"(__float_as_uint(a1.w)),
                          "r"(__float_as_uint(bb0)), "r"(__float_as_uint(bb1)));
                }
            }
        }
        if (lane == 0)
            asm volatile("mbarrier.arrive.shared.b64 _, [%0];"
                         :: "r"(emptyB + 8u * s) : "memory");
    }

    if (mode == 0) {
        #pragma unroll
        for (int mm = 0; mm < 2; mm++) {
            #pragma unroll
            for (int nn = 0; nn < 8; nn++) {
                int colL = wn * 64 + nn * 8 + q * 2;
                int rowL = wm * 32 + mm * 16 + g;
                size_t tb = ((size_t)by * NKT + bx * 4 + (colL >> 5)) * TILE_F;
                int kl = colL & 31;
                out[tb + apack_inner(rowL,     kl)]     = tf32r(c[mm][nn][0]);
                out[tb + apack_inner(rowL,     kl + 1)] = tf32r(c[mm][nn][1]);
                out[tb + apack_inner(rowL + 8, kl)]     = tf32r(c[mm][nn][2]);
                out[tb + apack_inner(rowL + 8, kl + 1)] = tf32r(c[mm][nn][3]);
            }
        }
    } else {
        const float b0v = bias[0];
        const size_t xoff = (size_t)NN * NN;
        const int rowBase = by * BM;
        const int colBase = bx * BN;
        #pragma unroll
        for (int mm = 0; mm < 2; mm++) {
            int row0 = rowBase + wm * 32 + mm * 16 + g;
            int row1 = row0 + 8;
            float ll0 = g_linl[row0] + b0v;
            float ll1 = g_linl[row1] + b0v;
            #pragma unroll
            for (int nn = 0; nn < 8; nn++) {
                int col = colBase + wn * 64 + nn * 8 + q * 2;
                float lr0 = g_linr[col];
                float lr1 = g_linr[col + 1];
                float v00 = c[mm][nn][0] + ll0 + lr0; v00 = v00 > 0.f ? v00 : 0.f;
                float v01 = c[mm][nn][1] + ll0 + lr1; v01 = v01 > 0.f ? v01 : 0.f;
                float v10 = c[mm][nn][2] + ll1 + lr0; v10 = v10 > 0.f ? v10 : 0.f;
                float v11 = c[mm][nn][3] + ll1 + lr1; v11 = v11 > 0.f ? v11 : 0.f;
                size_t b0i = (size_t)row0 * NN + col;
                size_t b1i = (size_t)row1 * NN + col;
                if (write_x_half) {
                    *(float2*)&out[xoff + b0i] = make_float2(v00, v01);
                    *(float2*)&out[xoff + b1i] = make_float2(v10, v11);
                }
                int2 m0 = *(const int2*)&mask[b0i];
                int2 m1 = *(const int2*)&mask[b1i];
                *(float2*)&out[b0i] = make_float2(m0.x ? v00 : 0.f, m0.y ? v01 : 0.f);
                *(float2*)&out[b1i] = make_float2(m1.x ? v10 : 0.f, m1.y ? v11 : 0.f);
            }
        }
    }
}

// ---------------------------------------------------------------------------
extern "C" void kernel_launch(void* const* d_in, const int* in_sizes, int n_in,
                              void* d_out, int out_size)
{
    const float* xl     = (const float*)d_in[0];
    const float* xr     = (const float*)d_in[1];
    const int*   mask   = (const int*)d_in[2];
    const float* matrix = (const float*)d_in[3];
    const float* bias   = (const float*)d_in[4];
    const float* wl     = (const float*)d_in[5];
    const float* bl     = (const float*)d_in[6];
    const float* wr     = (const float*)d_in[7];
    const float* br     = (const float*)d_in[8];
    float* out = (float*)d_out;

    int write_x_half = (out_size >= 2 * NN * NN) ? 1 : 0;

    cudaFuncSetAttribute(gemm_tc,
                         cudaFuncAttributeMaxDynamicSharedMemorySize, GEMM_SMEM);

    float *xm, *mt, *xlr, *xrr;
    cudaGetSymbolAddress((void**)&xm, g_xm);
    cudaGetSymbolAddress((void**)&mt, g_mt);
    cudaGetSymbolAddress((void**)&xlr, g_xlr);
    cudaGetSymbolAddress((void**)&xrr, g_xrr);

    // 1) prep: lin terms (exact), packed tf32 operands
    lin_kernel<<<1024, 256>>>(xl, xr, wl, bl, wr, br);
    pack_kernel<1><<<dim3(NN / 128, NKT), 256>>>(xl, xlr);   // A-packed x_l
    pack_kernel<0><<<dim3(NN / 128, NKT), 256>>>(xr, xrr);   // B-packed x_r
    packT_kernel<<<dim3(DD / 128, NKT), 256>>>(matrix, mt);  // B-packed M^T

    // 2) XM = tf32(x_l) @ M -> A-packed g_xm
    gemm_tc<<<dim3(DD / BN, NN / BM), 256, GEMM_SMEM>>>(
        xlr, mt, xm, nullptr, nullptr, 0, 0);

    // 3) S = XM @ tf32(x_r)^T + epilogue
    gemm_tc<<<dim3(NN / BN, NN / BM), 256, GEMM_SMEM>>>(
        xm, xrr, out, mask, bias, 1, write_x_half);
}